// round 15
// baseline (speedup 1.0000x reference)
#include <cuda_runtime.h>
#include <cuda_fp16.h>
#include <cstdint>
#include <math.h>

// ---------------------------------------------------------------------------
// Problem constants
// ---------------------------------------------------------------------------
#define TSEQ 2048
#define DIMC 2048
#define NH   16
#define NKV  4
#define HD   128
#define QKVN 3072
#define KOFF 2048
#define VOFF 2560

// ---------------------------------------------------------------------------
// Scratch (device globals — allocation-free per harness rules)
// ---------------------------------------------------------------------------
__device__ __half g_x[TSEQ * DIMC];       // fp16 x
__device__ __half g_wqkv[DIMC * QKVN];    // fp16 W_qkv (natural [K,N])
__device__ __half g_wo[DIMC * DIMC];      // fp16 W_o   (natural [K,N])
__device__ __half g_qkv[TSEQ * QKVN];     // qkv (fp16)
__device__ __half g_attn[TSEQ * DIMC];    // attn out (fp16)

// ---------------------------------------------------------------------------
// Helpers
// ---------------------------------------------------------------------------
__device__ __forceinline__ uint32_t smem_u32(const void* p) {
    uint32_t a;
    asm("{ .reg .u64 t; cvta.to.shared.u64 t, %1; cvt.u32.u64 %0, t; }" : "=r"(a) : "l"(p));
    return a;
}

#define CP_ASYNC16(dst, src) \
    asm volatile("cp.async.cg.shared.global [%0], [%1], 16;" :: "r"(dst), "l"(src) : "memory")
#define CP_COMMIT() asm volatile("cp.async.commit_group;" ::: "memory")
#define CP_WAIT(n)  asm volatile("cp.async.wait_group %0;" :: "n"(n) : "memory")

#define MMA_F16(c, a, b)                                                       \
    asm volatile(                                                              \
        "mma.sync.aligned.m16n8k16.row.col.f32.f16.f16.f32 "                   \
        "{%0,%1,%2,%3}, {%4,%5,%6,%7}, {%8,%9}, {%0,%1,%2,%3};"                \
        : "+f"((c)[0]), "+f"((c)[1]), "+f"((c)[2]), "+f"((c)[3])               \
        : "r"((a)[0]), "r"((a)[1]), "r"((a)[2]), "r"((a)[3]),                  \
          "r"((b)[0]), "r"((b)[1]))

#define LDSM_X4(r, addr)                                                       \
    asm volatile("ldmatrix.sync.aligned.m8n8.x4.shared.b16 {%0,%1,%2,%3}, [%4];" \
        : "=r"((r)[0]), "=r"((r)[1]), "=r"((r)[2]), "=r"((r)[3]) : "r"(addr))

#define LDSM_X4_T(r, addr)                                                     \
    asm volatile("ldmatrix.sync.aligned.m8n8.x4.trans.shared.b16 {%0,%1,%2,%3}, [%4];" \
        : "=r"((r)[0]), "=r"((r)[1]), "=r"((r)[2]), "=r"((r)[3]) : "r"(addr))

#define STSU32(addr, v) \
    asm volatile("st.shared.u32 [%0], %1;" :: "r"(addr), "r"(v) : "memory")

#define MBAR_INIT(addr, cnt) \
    asm volatile("mbarrier.init.shared.b64 [%0], %1;" :: "r"(addr), "r"(cnt) : "memory")
#define MBAR_ARRIVE(addr) \
    asm volatile("mbarrier.arrive.shared.b64 _, [%0];" :: "r"(addr) : "memory")
// .noinc: the async arrive COUNTS toward the expected arrival count
// (default variant pre-increments pend_count -> net zero -> deadlock).
#define MBAR_CPARRIVE(addr) \
    asm volatile("cp.async.mbarrier.arrive.noinc.shared.b64 [%0];" :: "r"(addr) : "memory")
#define MBAR_WAIT(addr, ph) do {                                                \
    asm volatile(                                                               \
        "{\n\t.reg .pred P;\n\t"                                                \
        "WL_%=:\n\t"                                                            \
        "mbarrier.try_wait.parity.acquire.cta.shared::cta.b64 P, [%0], %1, 0x989680;\n\t" \
        "@P bra.uni WD_%=;\n\t"                                                 \
        "bra.uni WL_%=;\n\t"                                                    \
        "WD_%=:\n\t}"                                                           \
        :: "r"(addr), "r"(ph) : "memory");                                      \
} while (0)

__device__ __forceinline__ uint32_t pack_h2(float a, float b) {
    __half2 h = __floats2half2_rn(a, b);
    return *(uint32_t*)&h;
}

// ---------------------------------------------------------------------------
// Dense fp16 GEMM (R11 config — proven): C[128,128] = A[128,K] @ B[K,N].
// 256 threads, 8 warps (4M x 2N), warp tile 32x64, 4-stage cp.async ring.
// ---------------------------------------------------------------------------
#define STAGES 4
#define ABYTES (128 * 128)
#define BBYTES (64 * 256)
#define STAGEB (ABYTES + BBYTES)

__global__ void __launch_bounds__(256, 1) gemm_h(
    const __half* __restrict__ A, int lda,
    const __half* __restrict__ B, int ldb,
    void* __restrict__ Cv, int ldc,
    int K, int outHalf)
{
    extern __shared__ char smem[];
    const uint32_t smemBase = smem_u32(smem);

    const int bx = blockIdx.x, by = blockIdx.y;
    const int m0 = by * 128;
    const int n0 = bx * 128;
    const int tid = threadIdx.x;
    const int wid = tid >> 5, lane = tid & 31;
    const int g = lane >> 2, tg = lane & 3;
    const int wm = (wid & 3) * 32;
    const int wn = (wid >> 2) * 64;
    const int nkt = K >> 6;

    int larow[4], lau8[4], lbrow[4], lbu8[4];
    uint32_t lasw[4], lbsw[4];
#pragma unroll
    for (int i = 0; i < 4; i++) {
        int id = tid + i * 256;
        larow[i] = id >> 3;
        lau8[i]  = (id & 7) * 8;
        lasw[i]  = (uint32_t)(larow[i] * 128 + (((id & 7) ^ (larow[i] & 7)) << 4));
        lbrow[i] = id >> 4;
        int bu   = id & 15;
        lbu8[i]  = bu * 8;
        lbsw[i]  = (uint32_t)(lbrow[i] * 256 + (((bu & 8) | ((bu & 7) ^ (lbrow[i] & 7))) << 4));
    }

#define ISSUE_STAGE(kt)                                                        \
    do {                                                                       \
        const uint32_t sA = smemBase + ((kt) & (STAGES - 1)) * STAGEB;         \
        const uint32_t sB = sA + ABYTES;                                       \
        _Pragma("unroll")                                                      \
        for (int i = 0; i < 4; i++) {                                          \
            CP_ASYNC16(sA + lasw[i],                                           \
                       A + (size_t)(m0 + larow[i]) * lda + (kt) * 64 + lau8[i]); \
            CP_ASYNC16(sB + lbsw[i],                                           \
                       B + (size_t)((kt) * 64 + lbrow[i]) * ldb + n0 + lbu8[i]); \
        }                                                                      \
        CP_COMMIT();                                                           \
    } while (0)

    const int r7 = lane & 7;
    const int b3 = (lane >> 3) & 1;
    const int b4 = (lane >> 4) & 1;
    uint32_t rowA[2], unitA[4];
#pragma unroll
    for (int m = 0; m < 2; m++) rowA[m] = (uint32_t)((wm + m * 16 + b3 * 8 + r7) * 128);
#pragma unroll
    for (int ks = 0; ks < 4; ks++) unitA[ks] = (uint32_t)(((2 * ks + b4) ^ r7) << 4);

    const int mi = lane >> 3;
    const int kb = (mi & 1) * 8 + r7;
    uint32_t btoff[4];
#pragma unroll
    for (int p = 0; p < 4; p++) {
        int u = ((wn + p * 16 + (mi >> 1) * 8) >> 3);
        btoff[p] = (uint32_t)(kb * 256 + (((u & 8) | ((u & 7) ^ r7)) << 4));
    }

    float acc[2][8][4];
#pragma unroll
    for (int m = 0; m < 2; m++)
#pragma unroll
        for (int n = 0; n < 8; n++)
#pragma unroll
            for (int q = 0; q < 4; q++) acc[m][n][q] = 0.f;

    for (int s = 0; s < STAGES - 1 && s < nkt; s++) ISSUE_STAGE(s);

    for (int kt = 0; kt < nkt; kt++) {
        CP_WAIT(STAGES - 2);
        __syncthreads();
        if (kt + STAGES - 1 < nkt) ISSUE_STAGE(kt + STAGES - 1);

        const uint32_t sA = smemBase + (kt & (STAGES - 1)) * STAGEB;
        const uint32_t sB = sA + ABYTES;

#pragma unroll
        for (int ks = 0; ks < 4; ks++) {
            uint32_t af[2][4];
            LDSM_X4(af[0], sA + rowA[0] + unitA[ks]);
            LDSM_X4(af[1], sA + rowA[1] + unitA[ks]);
            uint32_t bfr[4][4];
#pragma unroll
            for (int p = 0; p < 4; p++)
                LDSM_X4_T(bfr[p], sB + ks * 4096 + btoff[p]);
#pragma unroll
            for (int m = 0; m < 2; m++)
#pragma unroll
                for (int n = 0; n < 8; n++)
                    MMA_F16(acc[m][n], af[m], &bfr[n >> 1][(n & 1) * 2]);
        }
    }

#pragma unroll
    for (int m = 0; m < 2; m++) {
        const int r0 = m0 + wm + m * 16 + g;
#pragma unroll
        for (int n = 0; n < 8; n++) {
            const int col = n0 + wn + n * 8 + 2 * tg;
            if (outHalf) {
                __half* C = (__half*)Cv;
                *(uint32_t*)(C + (size_t)r0 * ldc + col) =
                    pack_h2(acc[m][n][0], acc[m][n][1]);
                *(uint32_t*)(C + (size_t)(r0 + 8) * ldc + col) =
                    pack_h2(acc[m][n][2], acc[m][n][3]);
            } else {
                float* C = (float*)Cv;
                *(float2*)(C + (size_t)r0 * ldc + col) =
                    make_float2(acc[m][n][0], acc[m][n][1]);
                *(float2*)(C + (size_t)(r0 + 8) * ldc + col) =
                    make_float2(acc[m][n][2], acc[m][n][3]);
            }
        }
    }
#undef ISSUE_STAGE
}

// ---------------------------------------------------------------------------
// Fused causal flash attention, warp-skewed via mbarrier producer/consumer.
// 288 threads: warps 0-7 compute (16 q rows each), warp 8 = producer.
// smem: Qs 32KB | Ps 32KB | ring NSLOT x 16KB | mbarriers.
// No __syncthreads in the mainloop: per-slot full (count 32, cp.async .noinc
// arrive) and empty (count 8) barriers let warps skew, overlapping one warp's
// EX2 softmax with another's HMMA.
// ---------------------------------------------------------------------------
#define NSLOT 6
#define FSM_Q 0
#define FSM_P 32768
#define FSM_R 65536
#define FSM_BAR (FSM_R + NSLOT * 16384)      // full[6] then empty[6], 8B each
#define FSM_TOTAL (FSM_BAR + 128)

__global__ void __launch_bounds__(288, 1) flash_attn()
{
    extern __shared__ char smem[];
    const uint32_t sb = smem_u32(smem);

    const int h     = blockIdx.y;
    const int itile = (int)gridDim.x - 1 - (int)blockIdx.x;  // heavy-first
    const int kvh   = h >> 2;
    const int tid   = threadIdx.x;
    const int lane  = tid & 31;
    const int wid   = tid >> 5;

    const __half* Qg = g_qkv + (size_t)(itile * 128) * QKVN + h * HD;
    const __half* Kg = g_qkv + KOFF + (size_t)kvh * HD;
    const __half* Vg = g_qkv + VOFF + (size_t)kvh * HD;

    if (tid == 0) {
#pragma unroll
        for (int s = 0; s < NSLOT; s++) {
            MBAR_INIT(sb + FSM_BAR + 8 * s, 32);           // full: 32 producer lanes
            MBAR_INIT(sb + FSM_BAR + 48 + 8 * s, 8);       // empty: 8 consumer warps
        }
    }

    // Q tile load (consumers, tid 0..255): 2 chunks x 1024 16B units
    if (wid < 8) {
#pragma unroll
        for (int i = 0; i < 4; i++) {
            int id = tid + i * 256;
            int row = id >> 3, u = id & 7;
            uint32_t sw = (uint32_t)(row * 128 + ((u ^ (row & 7)) << 4));
#pragma unroll
            for (int kt = 0; kt < 2; kt++)
                CP_ASYNC16(sb + FSM_Q + kt * 16384 + sw,
                           Qg + (size_t)row * QKVN + kt * 64 + u * 8);
        }
        CP_COMMIT();
        CP_WAIT(0);
    }
    __syncthreads();

    const int nch = 4 * (itile + 1);

    if (wid == 8) {
        // ---------------- producer warp ----------------
        int pslot = 0, pphase = 1;
        const int l3 = lane >> 3, u7 = lane & 7;
        const int l4 = lane >> 4, u15 = lane & 15;
        for (int c = 0; c < nch; c++) {
            MBAR_WAIT(sb + FSM_BAR + 48 + 8 * pslot, pphase);
            const uint32_t dst = sb + FSM_R + pslot * 16384;
            const int jt = c >> 2, ty = (c >> 1) & 1, kt = c & 1;
            if (ty == 0) {
#pragma unroll 8
                for (int j = 0; j < 32; j++) {
                    int row = l3 + 4 * j;
                    uint32_t sw = (uint32_t)(row * 128 + ((u7 ^ (row & 7)) << 4));
                    CP_ASYNC16(dst + sw,
                               Kg + (size_t)(jt * 128 + row) * QKVN + kt * 64 + u7 * 8);
                }
            } else {
#pragma unroll 8
                for (int j = 0; j < 32; j++) {
                    int row = l4 + 2 * j;
                    uint32_t sw = (uint32_t)(row * 256 +
                                 (((u15 & 8) | ((u15 & 7) ^ (row & 7))) << 4));
                    CP_ASYNC16(dst + sw,
                               Vg + (size_t)(jt * 128 + kt * 64 + row) * QKVN + u15 * 8);
                }
            }
            MBAR_CPARRIVE(sb + FSM_BAR + 8 * pslot);
            if (++pslot == NSLOT) { pslot = 0; pphase ^= 1; }
        }
    } else {
        // ---------------- consumer warps ----------------
        const int g = lane >> 2, tg = lane & 3;
        const int wr = wid * 16;
        const int r7 = lane & 7;
        const int b3 = (lane >> 3) & 1;
        const int b4 = (lane >> 4) & 1;
        const uint32_t rowAf = (uint32_t)((wr + b3 * 8 + r7) * 128);
        uint32_t rowB[8], unitA[4], unitB[4];
#pragma unroll
        for (int p = 0; p < 8; p++) rowB[p] = (uint32_t)(((2 * p + b4) * 8 + r7) * 128);
#pragma unroll
        for (int ks = 0; ks < 4; ks++) {
            unitA[ks] = (uint32_t)(((2 * ks + b4) ^ r7) << 4);
            unitB[ks] = (uint32_t)(((2 * ks + b3) ^ r7) << 4);
        }
        const int mi = lane >> 3;
        const int kb = (mi & 1) * 8 + r7;
        uint32_t vtoff[8];
#pragma unroll
        for (int p = 0; p < 8; p++) {
            int u = 2 * p + (mi >> 1);
            vtoff[p] = (uint32_t)(kb * 256 + (((u & 8) | ((u & 7) ^ r7)) << 4));
        }

        float S[16][4], O[16][4];
#pragma unroll
        for (int n = 0; n < 16; n++)
#pragma unroll
            for (int q = 0; q < 4; q++) O[n][q] = 0.f;
        float mrow0 = -1e30f, mrow1 = -1e30f;
        float lsum0 = 0.f, lsum1 = 0.f;

        const int rl0 = wr + g;
        const int rl1 = wr + g + 8;
        const float scl2 = 0.08838834764831845f * 1.4426950408889634f;  // scl*log2e

        int cslot = 0, cphase = 0;
        for (int c = 0; c < nch; c++) {
            MBAR_WAIT(sb + FSM_BAR + 8 * cslot, cphase);
            const uint32_t sBb = sb + FSM_R + cslot * 16384;
            const int jt = c >> 2, ty = (c >> 1) & 1, kt = c & 1;

            if (ty == 0) {
                if (kt == 0) {
#pragma unroll
                    for (int n = 0; n < 16; n++)
#pragma unroll
                        for (int q = 0; q < 4; q++) S[n][q] = 0.f;
                }
                const uint32_t sAq = sb + FSM_Q + kt * 16384;
#pragma unroll
                for (int ks = 0; ks < 4; ks++) {
                    uint32_t af[4];
                    LDSM_X4(af, sAq + rowAf + unitA[ks]);
                    uint32_t bfr[8][4];
#pragma unroll
                    for (int p = 0; p < 8; p++) LDSM_X4(bfr[p], sBb + rowB[p] + unitB[ks]);
#pragma unroll
                    for (int n = 0; n < 16; n++)
                        MMA_F16(S[n], af, &bfr[n >> 1][(n & 1) * 2]);
                }
                // release slot before scalar softmax work
                __syncwarp();
                if (lane == 0) MBAR_ARRIVE(sb + FSM_BAR + 48 + 8 * cslot);

                if (kt == 1) {
                    // ---- online softmax (log2 domain) ----
#pragma unroll
                    for (int n = 0; n < 16; n++)
#pragma unroll
                        for (int q = 0; q < 4; q++) S[n][q] *= scl2;

                    if (jt == itile) {
#pragma unroll
                        for (int n = 0; n < 16; n++) {
                            const int c0 = n * 8 + 2 * tg;
                            if (c0 > rl0)     S[n][0] = -1e30f;
                            if (c0 + 1 > rl0) S[n][1] = -1e30f;
                            if (c0 > rl1)     S[n][2] = -1e30f;
                            if (c0 + 1 > rl1) S[n][3] = -1e30f;
                        }
                    }

                    float tm0 = -1e30f, tm1 = -1e30f;
#pragma unroll
                    for (int n = 0; n < 16; n++) {
                        tm0 = fmaxf(tm0, fmaxf(S[n][0], S[n][1]));
                        tm1 = fmaxf(tm1, fmaxf(S[n][2], S[n][3]));
                    }
                    tm0 = fmaxf(tm0, __shfl_xor_sync(0xFFFFFFFF, tm0, 1));
                    tm0 = fmaxf(tm0, __shfl_xor_sync(0xFFFFFFFF, tm0, 2));
                    tm1 = fmaxf(tm1, __shfl_xor_sync(0xFFFFFFFF, tm1, 1));
                    tm1 = fmaxf(tm1, __shfl_xor_sync(0xFFFFFFFF, tm1, 2));

                    const float mn0 = fmaxf(mrow0, tm0);
                    const float mn1 = fmaxf(mrow1, tm1);
                    const float a0 = exp2f(mrow0 - mn0);
                    const float a1 = exp2f(mrow1 - mn1);
                    mrow0 = mn0; mrow1 = mn1;

                    float s0 = 0.f, s1 = 0.f;
#pragma unroll
                    for (int n = 0; n < 16; n++) {
                        S[n][0] = exp2f(S[n][0] - mn0);
                        S[n][1] = exp2f(S[n][1] - mn0);
                        S[n][2] = exp2f(S[n][2] - mn1);
                        S[n][3] = exp2f(S[n][3] - mn1);
                        s0 += S[n][0] + S[n][1];
                        s1 += S[n][2] + S[n][3];
                    }
                    s0 += __shfl_xor_sync(0xFFFFFFFF, s0, 1);
                    s0 += __shfl_xor_sync(0xFFFFFFFF, s0, 2);
                    s1 += __shfl_xor_sync(0xFFFFFFFF, s1, 1);
                    s1 += __shfl_xor_sync(0xFFFFFFFF, s1, 2);
                    lsum0 = lsum0 * a0 + s0;
                    lsum1 = lsum1 * a1 + s1;

#pragma unroll
                    for (int n = 0; n < 16; n++) {
                        O[n][0] *= a0; O[n][1] *= a0;
                        O[n][2] *= a1; O[n][3] *= a1;
                    }

                    // write P (fp16) into Ps; own-warp rows only
#pragma unroll
                    for (int n = 0; n < 16; n++) {
                        const uint32_t a =
                            sb + FSM_P + ((n >> 3) * 16384) + rl0 * 128 +
                            (((n & 7) ^ (rl0 & 7)) << 4) + tg * 4;
                        STSU32(a, pack_h2(S[n][0], S[n][1]));
                        STSU32(a + 1024, pack_h2(S[n][2], S[n][3]));
                    }
                    __syncwarp();   // P visible to own-warp LDSM in PV phase
                }
            } else {
                // ---- PV: A = P chunk kt (j-half), B = V chunk (trans) ----
                const uint32_t sAp = sb + FSM_P + kt * 16384;
#pragma unroll
                for (int ks = 0; ks < 4; ks++) {
                    uint32_t af[4];
                    LDSM_X4(af, sAp + rowAf + unitA[ks]);
                    uint32_t bfr[8][4];
#pragma unroll
                    for (int p = 0; p < 8; p++)
                        LDSM_X4_T(bfr[p], sBb + ks * 4096 + vtoff[p]);
#pragma unroll
                    for (int n = 0; n < 16; n++)
                        MMA_F16(O[n], af, &bfr[n >> 1][(n & 1) * 2]);
                }
                __syncwarp();
                if (lane == 0) MBAR_ARRIVE(sb + FSM_BAR + 48 + 8 * cslot);
            }

            if (++cslot == NSLOT) { cslot = 0; cphase ^= 1; }
        }

        // epilogue: normalize, store fp16 to g_attn
        const float inv0 = 1.0f / lsum0;
        const float inv1 = 1.0f / lsum1;
        const int gr0 = itile * 128 + rl0;
        const int gr1 = itile * 128 + rl1;
#pragma unroll
        for (int n = 0; n < 16; n++) {
            const int col = h * HD + n * 8 + 2 * tg;
            *(uint32_t*)(g_attn + (size_t)gr0 * DIMC + col) =
                pack_h2(O[n][0] * inv0, O[n][1] * inv0);
            *(uint32_t*)(g_attn + (size_t)gr1 * DIMC + col) =
                pack_h2(O[n][2] * inv1, O[n][3] * inv1);
        }
    }
}

// ---------------------------------------------------------------------------
// Fused fp32 -> fp16 convert for x, W_qkv, W_o (float4 granules)
// ---------------------------------------------------------------------------
#define N4_X  (TSEQ * DIMC / 4)
#define N4_W1 (DIMC * QKVN / 4)
#define N4_W2 (DIMC * DIMC / 4)

__global__ void k_cvt_all(const float* __restrict__ sx,
                          const float* __restrict__ sw1,
                          const float* __restrict__ sw2)
{
    int i = blockIdx.x * blockDim.x + threadIdx.x;
    const float* src;
    __half* dst;
    int off;
    if (i < N4_X)              { src = sx;  dst = g_x;    off = i; }
    else if (i < N4_X + N4_W1) { src = sw1; dst = g_wqkv; off = i - N4_X; }
    else if (i < N4_X + N4_W1 + N4_W2) { src = sw2; dst = g_wo; off = i - N4_X - N4_W1; }
    else return;
    float4 v = ((const float4*)src)[off];
    uint2 o;
    o.x = pack_h2(v.x, v.y);
    o.y = pack_h2(v.z, v.w);
    ((uint2*)dst)[off] = o;
}

// ---------------------------------------------------------------------------
// Host side
// ---------------------------------------------------------------------------
extern "C" void kernel_launch(void* const* d_in, const int* in_sizes, int n_in,
                              void* d_out, int out_size)
{
    const float* x    = (const float*)d_in[0];
    const float* Wqkv = (const float*)d_in[1];
    const float* Wo   = (const float*)d_in[2];

    void *px, *pwqkv, *pwo, *pqkv, *pattn;
    cudaGetSymbolAddress(&px, g_x);
    cudaGetSymbolAddress(&pwqkv, g_wqkv);
    cudaGetSymbolAddress(&pwo, g_wo);
    cudaGetSymbolAddress(&pqkv, g_qkv);
    cudaGetSymbolAddress(&pattn, g_attn);

    const int smemSz = STAGES * STAGEB;   // 128 KB
    cudaFuncSetAttribute(gemm_h, cudaFuncAttributeMaxDynamicSharedMemorySize, smemSz);
    cudaFuncSetAttribute(flash_attn, cudaFuncAttributeMaxDynamicSharedMemorySize, FSM_TOTAL);

    // 1) fused fp32 -> fp16 conversion (x, W_qkv, W_o)
    {
        const int total = N4_X + N4_W1 + N4_W2;
        k_cvt_all<<<(total + 255) / 256, 256>>>(x, Wqkv, Wo);
    }

    // 2) qkv = x_h @ W_qkv  [2048,3072] (fp16 out)
    gemm_h<<<dim3(QKVN / 128, TSEQ / 128), 256, smemSz>>>(
        (const __half*)px, DIMC, (const __half*)pwqkv, QKVN,
        pqkv, QKVN, DIMC, 1);

    // 3) fused causal attention -> g_attn (fp16)
    flash_attn<<<dim3(TSEQ / 128, NH), 288, FSM_TOTAL>>>();

    // 4) out = attn @ W_o (fp32 out)
    gemm_h<<<dim3(DIMC / 128, TSEQ / 128), 256, smemSz>>>(
        (const __half*)pattn, DIMC, (const __half*)pwo, DIMC,
        d_out, DIMC, DIMC, 0);
}

// round 17
// speedup vs baseline: 1.0664x; 1.0664x over previous
#include <cuda_runtime.h>
#include <cuda_fp16.h>
#include <cstdint>
#include <math.h>

// ---------------------------------------------------------------------------
// Problem constants
// ---------------------------------------------------------------------------
#define TSEQ 2048
#define DIMC 2048
#define NH   16
#define NKV  4
#define HD   128
#define QKVN 3072
#define KOFF 2048
#define VOFF 2560

// ---------------------------------------------------------------------------
// Scratch (device globals — allocation-free per harness rules)
// ---------------------------------------------------------------------------
__device__ __half g_x[TSEQ * DIMC];       // fp16 x
__device__ __half g_wqkv[DIMC * QKVN];    // fp16 W_qkv (natural [K,N])
__device__ __half g_wo[DIMC * DIMC];      // fp16 W_o   (natural [K,N])
__device__ __half g_qkv[TSEQ * QKVN];     // qkv (fp16)
__device__ __half g_attn[TSEQ * DIMC];    // attn out (fp16)

// ---------------------------------------------------------------------------
// Helpers
// ---------------------------------------------------------------------------
__device__ __forceinline__ uint32_t smem_u32(const void* p) {
    uint32_t a;
    asm("{ .reg .u64 t; cvta.to.shared.u64 t, %1; cvt.u32.u64 %0, t; }" : "=r"(a) : "l"(p));
    return a;
}

#define CP_ASYNC16(dst, src) \
    asm volatile("cp.async.cg.shared.global [%0], [%1], 16;" :: "r"(dst), "l"(src) : "memory")
#define CP_COMMIT() asm volatile("cp.async.commit_group;" ::: "memory")
#define CP_WAIT(n)  asm volatile("cp.async.wait_group %0;" :: "n"(n) : "memory")

#define MMA_F16(c, a, b)                                                       \
    asm volatile(                                                              \
        "mma.sync.aligned.m16n8k16.row.col.f32.f16.f16.f32 "                   \
        "{%0,%1,%2,%3}, {%4,%5,%6,%7}, {%8,%9}, {%0,%1,%2,%3};"                \
        : "+f"((c)[0]), "+f"((c)[1]), "+f"((c)[2]), "+f"((c)[3])               \
        : "r"((a)[0]), "r"((a)[1]), "r"((a)[2]), "r"((a)[3]),                  \
          "r"((b)[0]), "r"((b)[1]))

#define LDSM_X4(r, addr)                                                       \
    asm volatile("ldmatrix.sync.aligned.m8n8.x4.shared.b16 {%0,%1,%2,%3}, [%4];" \
        : "=r"((r)[0]), "=r"((r)[1]), "=r"((r)[2]), "=r"((r)[3]) : "r"(addr))

#define LDSM_X4_T(r, addr)                                                     \
    asm volatile("ldmatrix.sync.aligned.m8n8.x4.trans.shared.b16 {%0,%1,%2,%3}, [%4];" \
        : "=r"((r)[0]), "=r"((r)[1]), "=r"((r)[2]), "=r"((r)[3]) : "r"(addr))

#define STSU32(addr, v) \
    asm volatile("st.shared.u32 [%0], %1;" :: "r"(addr), "r"(v) : "memory")

__device__ __forceinline__ uint32_t pack_h2(float a, float b) {
    __half2 h = __floats2half2_rn(a, b);
    return *(uint32_t*)&h;
}

// ---------------------------------------------------------------------------
// Dense fp16 GEMM (R11 config — proven): C[128,128] = A[128,K] @ B[K,N].
// 256 threads, 8 warps (4M x 2N), warp tile 32x64, 4-stage cp.async ring.
// Tail race fixed with empty commit-group padding.
// ---------------------------------------------------------------------------
#define STAGES 4
#define ABYTES (128 * 128)
#define BBYTES (64 * 256)
#define STAGEB (ABYTES + BBYTES)

__global__ void __launch_bounds__(256, 1) gemm_h(
    const __half* __restrict__ A, int lda,
    const __half* __restrict__ B, int ldb,
    void* __restrict__ Cv, int ldc,
    int K, int outHalf)
{
    extern __shared__ char smem[];
    const uint32_t smemBase = smem_u32(smem);

    const int bx = blockIdx.x, by = blockIdx.y;
    const int m0 = by * 128;
    const int n0 = bx * 128;
    const int tid = threadIdx.x;
    const int wid = tid >> 5, lane = tid & 31;
    const int g = lane >> 2, tg = lane & 3;
    const int wm = (wid & 3) * 32;
    const int wn = (wid >> 2) * 64;
    const int nkt = K >> 6;

    int larow[4], lau8[4], lbrow[4], lbu8[4];
    uint32_t lasw[4], lbsw[4];
#pragma unroll
    for (int i = 0; i < 4; i++) {
        int id = tid + i * 256;
        larow[i] = id >> 3;
        lau8[i]  = (id & 7) * 8;
        lasw[i]  = (uint32_t)(larow[i] * 128 + (((id & 7) ^ (larow[i] & 7)) << 4));
        lbrow[i] = id >> 4;
        int bu   = id & 15;
        lbu8[i]  = bu * 8;
        lbsw[i]  = (uint32_t)(lbrow[i] * 256 + (((bu & 8) | ((bu & 7) ^ (lbrow[i] & 7))) << 4));
    }

#define ISSUE_STAGE(kt)                                                        \
    do {                                                                       \
        const uint32_t sA = smemBase + ((kt) & (STAGES - 1)) * STAGEB;         \
        const uint32_t sB = sA + ABYTES;                                       \
        _Pragma("unroll")                                                      \
        for (int i = 0; i < 4; i++) {                                          \
            CP_ASYNC16(sA + lasw[i],                                           \
                       A + (size_t)(m0 + larow[i]) * lda + (kt) * 64 + lau8[i]); \
            CP_ASYNC16(sB + lbsw[i],                                           \
                       B + (size_t)((kt) * 64 + lbrow[i]) * ldb + n0 + lbu8[i]); \
        }                                                                      \
        CP_COMMIT();                                                           \
    } while (0)

    const int r7 = lane & 7;
    const int b3 = (lane >> 3) & 1;
    const int b4 = (lane >> 4) & 1;
    uint32_t rowA[2], unitA[4];
#pragma unroll
    for (int m = 0; m < 2; m++) rowA[m] = (uint32_t)((wm + m * 16 + b3 * 8 + r7) * 128);
#pragma unroll
    for (int ks = 0; ks < 4; ks++) unitA[ks] = (uint32_t)(((2 * ks + b4) ^ r7) << 4);

    const int mi = lane >> 3;
    const int kb = (mi & 1) * 8 + r7;
    uint32_t btoff[4];
#pragma unroll
    for (int p = 0; p < 4; p++) {
        int u = ((wn + p * 16 + (mi >> 1) * 8) >> 3);
        btoff[p] = (uint32_t)(kb * 256 + (((u & 8) | ((u & 7) ^ r7)) << 4));
    }

    float acc[2][8][4];
#pragma unroll
    for (int m = 0; m < 2; m++)
#pragma unroll
        for (int n = 0; n < 8; n++)
#pragma unroll
            for (int q = 0; q < 4; q++) acc[m][n][q] = 0.f;

    for (int s = 0; s < STAGES - 1; s++) {
        if (s < nkt) ISSUE_STAGE(s); else CP_COMMIT();
    }

    for (int kt = 0; kt < nkt; kt++) {
        CP_WAIT(STAGES - 2);
        __syncthreads();
        if (kt + STAGES - 1 < nkt) ISSUE_STAGE(kt + STAGES - 1);
        else CP_COMMIT();   // empty group keeps wait_group counting exact

        const uint32_t sA = smemBase + (kt & (STAGES - 1)) * STAGEB;
        const uint32_t sB = sA + ABYTES;

#pragma unroll
        for (int ks = 0; ks < 4; ks++) {
            uint32_t af[2][4];
            LDSM_X4(af[0], sA + rowA[0] + unitA[ks]);
            LDSM_X4(af[1], sA + rowA[1] + unitA[ks]);
            uint32_t bfr[4][4];
#pragma unroll
            for (int p = 0; p < 4; p++)
                LDSM_X4_T(bfr[p], sB + ks * 4096 + btoff[p]);
#pragma unroll
            for (int m = 0; m < 2; m++)
#pragma unroll
                for (int n = 0; n < 8; n++)
                    MMA_F16(acc[m][n], af[m], &bfr[n >> 1][(n & 1) * 2]);
        }
    }

#pragma unroll
    for (int m = 0; m < 2; m++) {
        const int r0 = m0 + wm + m * 16 + g;
#pragma unroll
        for (int n = 0; n < 8; n++) {
            const int col = n0 + wn + n * 8 + 2 * tg;
            if (outHalf) {
                __half* C = (__half*)Cv;
                *(uint32_t*)(C + (size_t)r0 * ldc + col) =
                    pack_h2(acc[m][n][0], acc[m][n][1]);
                *(uint32_t*)(C + (size_t)(r0 + 8) * ldc + col) =
                    pack_h2(acc[m][n][2], acc[m][n][3]);
            } else {
                float* C = (float*)Cv;
                *(float2*)(C + (size_t)r0 * ldc + col) =
                    make_float2(acc[m][n][0], acc[m][n][1]);
                *(float2*)(C + (size_t)(r0 + 8) * ldc + col) =
                    make_float2(acc[m][n][2], acc[m][n][3]);
            }
        }
    }
#undef ISSUE_STAGE
}

// ---------------------------------------------------------------------------
// Fused causal flash attention (fp16 mma, fp32 accum), cooperative loading.
// One CTA per (q-row-tile, head). 8 warps x 16 q rows, 256 threads.
// smem: Qs 32KB | Ps 32KB | ring 4 x 32KB = 192KB.
// 32KB slot = whole K tile or whole V tile; 2 syncs per j-tile.
// cp.async group counting made exact with empty commit-group padding
// (fixes itile=0 head race and the latent tail race).
// ---------------------------------------------------------------------------
#define FSM_Q 0
#define FSM_P 32768
#define FSM_R 65536
#define FSM_TOTAL (FSM_R + 4 * 32768)   // 192KB

__global__ void __launch_bounds__(256, 1) flash_attn()
{
    extern __shared__ char smem[];
    const uint32_t sb = smem_u32(smem);

    const int h     = blockIdx.y;
    const int itile = (int)gridDim.x - 1 - (int)blockIdx.x;  // heavy-first
    const int kvh   = h >> 2;
    const int tid   = threadIdx.x;
    const int lane  = tid & 31;
    const int wid   = tid >> 5;
    const int g     = lane >> 2, tg = lane & 3;
    const int wr    = wid * 16;

    int lrow[4], lu8[4], vrow[4], vu8[4];
    uint32_t lsw[4], vsw[4];
#pragma unroll
    for (int i = 0; i < 4; i++) {
        int id = tid + i * 256;
        lrow[i] = id >> 3;
        lu8[i]  = (id & 7) * 8;
        lsw[i]  = (uint32_t)(lrow[i] * 128 + (((id & 7) ^ (lrow[i] & 7)) << 4));
        vrow[i] = id >> 4;
        int vu  = id & 15;
        vu8[i]  = vu * 8;
        vsw[i]  = (uint32_t)(vrow[i] * 256 + (((vu & 8) | ((vu & 7) ^ (vrow[i] & 7))) << 4));
    }

    const __half* Qg = g_qkv + (size_t)(itile * 128) * QKVN + h * HD;
    const __half* Kg = g_qkv + KOFF + (size_t)kvh * HD;
    const __half* Vg = g_qkv + VOFF + (size_t)kvh * HD;

    // Q tile: 2 halves (d), one commit group
#pragma unroll
    for (int kt = 0; kt < 2; kt++)
#pragma unroll
        for (int i = 0; i < 4; i++)
            CP_ASYNC16(sb + FSM_Q + kt * 16384 + lsw[i],
                       Qg + (size_t)lrow[i] * QKVN + kt * 64 + lu8[i]);
    CP_COMMIT();

    const int nch = 2 * (itile + 1);   // K slot + V slot per j-tile

#define ISSUE_CHUNK(c)                                                         \
    do {                                                                       \
        const int _jt = (c) >> 1, _ty = (c) & 1;                               \
        const uint32_t _dst = sb + FSM_R + ((c) & 3) * 32768;                  \
        if (_ty == 0) {                                                        \
            _Pragma("unroll")                                                  \
            for (int _kt = 0; _kt < 2; _kt++)                                  \
                _Pragma("unroll")                                              \
                for (int i = 0; i < 4; i++)                                    \
                    CP_ASYNC16(_dst + _kt * 16384 + lsw[i],                    \
                               Kg + (size_t)(_jt * 128 + lrow[i]) * QKVN + _kt * 64 + lu8[i]); \
        } else {                                                               \
            _Pragma("unroll")                                                  \
            for (int _kt = 0; _kt < 2; _kt++)                                  \
                _Pragma("unroll")                                              \
                for (int i = 0; i < 4; i++)                                    \
                    CP_ASYNC16(_dst + _kt * 16384 + vsw[i],                    \
                               Vg + (size_t)(_jt * 128 + _kt * 64 + vrow[i]) * QKVN + vu8[i]); \
        }                                                                      \
        CP_COMMIT();                                                           \
    } while (0)

    // prologue: always 3 commit groups (empty-padded) so counting is exact
    for (int c = 0; c < 3; c++) {
        if (c < nch) ISSUE_CHUNK(c); else CP_COMMIT();
    }

    const int r7 = lane & 7;
    const int b3 = (lane >> 3) & 1;
    const int b4 = (lane >> 4) & 1;
    const uint32_t rowAf = (uint32_t)((wr + b3 * 8 + r7) * 128);
    uint32_t rowB[8], unitA[4], unitB[4];
#pragma unroll
    for (int p = 0; p < 8; p++) rowB[p] = (uint32_t)(((2 * p + b4) * 8 + r7) * 128);
#pragma unroll
    for (int ks = 0; ks < 4; ks++) {
        unitA[ks] = (uint32_t)(((2 * ks + b4) ^ r7) << 4);
        unitB[ks] = (uint32_t)(((2 * ks + b3) ^ r7) << 4);
    }
    const int mi = lane >> 3;
    const int kb = (mi & 1) * 8 + r7;
    uint32_t vtoff[8];
#pragma unroll
    for (int p = 0; p < 8; p++) {
        int u = 2 * p + (mi >> 1);
        vtoff[p] = (uint32_t)(kb * 256 + (((u & 8) | ((u & 7) ^ r7)) << 4));
    }

    float S[16][4], O[16][4];
#pragma unroll
    for (int n = 0; n < 16; n++)
#pragma unroll
        for (int q = 0; q < 4; q++) O[n][q] = 0.f;
    float mrow0 = -1e30f, mrow1 = -1e30f;
    float lsum0 = 0.f, lsum1 = 0.f;

    const int rl0 = wr + g;
    const int rl1 = wr + g + 8;
    const float scl2 = 0.08838834764831845f * 1.4426950408889634f;  // scl*log2e

    for (int c = 0; c < nch; c++) {
        CP_WAIT(2);
        __syncthreads();
        if (c + 3 < nch) ISSUE_CHUNK(c + 3);
        else CP_COMMIT();   // empty group keeps counting exact

        const int jt = c >> 1, ty = c & 1;
        const uint32_t slot = sb + FSM_R + (c & 3) * 32768;

        if (ty == 0) {
            // ---- S = Q K^T over both d-halves ----
#pragma unroll
            for (int n = 0; n < 16; n++)
#pragma unroll
                for (int q = 0; q < 4; q++) S[n][q] = 0.f;
#pragma unroll
            for (int kt = 0; kt < 2; kt++) {
                const uint32_t sAq = sb + FSM_Q + kt * 16384;
                const uint32_t sBb = slot + kt * 16384;
#pragma unroll
                for (int ks = 0; ks < 4; ks++) {
                    uint32_t af[4];
                    LDSM_X4(af, sAq + rowAf + unitA[ks]);
                    uint32_t bfr[8][4];
#pragma unroll
                    for (int p = 0; p < 8; p++) LDSM_X4(bfr[p], sBb + rowB[p] + unitB[ks]);
#pragma unroll
                    for (int n = 0; n < 16; n++)
                        MMA_F16(S[n], af, &bfr[n >> 1][(n & 1) * 2]);
                }
            }

            // ---- online softmax (log2 domain) ----
#pragma unroll
            for (int n = 0; n < 16; n++)
#pragma unroll
                for (int q = 0; q < 4; q++) S[n][q] *= scl2;

            if (jt == itile) {
#pragma unroll
                for (int n = 0; n < 16; n++) {
                    const int c0 = n * 8 + 2 * tg;
                    if (c0 > rl0)     S[n][0] = -1e30f;
                    if (c0 + 1 > rl0) S[n][1] = -1e30f;
                    if (c0 > rl1)     S[n][2] = -1e30f;
                    if (c0 + 1 > rl1) S[n][3] = -1e30f;
                }
            }

            float tm0 = -1e30f, tm1 = -1e30f;
#pragma unroll
            for (int n = 0; n < 16; n++) {
                tm0 = fmaxf(tm0, fmaxf(S[n][0], S[n][1]));
                tm1 = fmaxf(tm1, fmaxf(S[n][2], S[n][3]));
            }
            tm0 = fmaxf(tm0, __shfl_xor_sync(0xFFFFFFFF, tm0, 1));
            tm0 = fmaxf(tm0, __shfl_xor_sync(0xFFFFFFFF, tm0, 2));
            tm1 = fmaxf(tm1, __shfl_xor_sync(0xFFFFFFFF, tm1, 1));
            tm1 = fmaxf(tm1, __shfl_xor_sync(0xFFFFFFFF, tm1, 2));

            const float mn0 = fmaxf(mrow0, tm0);
            const float mn1 = fmaxf(mrow1, tm1);
            const float a0 = exp2f(mrow0 - mn0);
            const float a1 = exp2f(mrow1 - mn1);
            mrow0 = mn0; mrow1 = mn1;

            float s0 = 0.f, s1 = 0.f;
#pragma unroll
            for (int n = 0; n < 16; n++) {
                S[n][0] = exp2f(S[n][0] - mn0);
                S[n][1] = exp2f(S[n][1] - mn0);
                S[n][2] = exp2f(S[n][2] - mn1);
                S[n][3] = exp2f(S[n][3] - mn1);
                s0 += S[n][0] + S[n][1];
                s1 += S[n][2] + S[n][3];
            }
            s0 += __shfl_xor_sync(0xFFFFFFFF, s0, 1);
            s0 += __shfl_xor_sync(0xFFFFFFFF, s0, 2);
            s1 += __shfl_xor_sync(0xFFFFFFFF, s1, 1);
            s1 += __shfl_xor_sync(0xFFFFFFFF, s1, 2);
            lsum0 = lsum0 * a0 + s0;
            lsum1 = lsum1 * a1 + s1;

#pragma unroll
            for (int n = 0; n < 16; n++) {
                O[n][0] *= a0; O[n][1] *= a0;
                O[n][2] *= a1; O[n][3] *= a1;
            }

            // write P (fp16) into Ps; own-warp rows only
#pragma unroll
            for (int n = 0; n < 16; n++) {
                const uint32_t a =
                    sb + FSM_P + ((n >> 3) * 16384) + rl0 * 128 +
                    (((n & 7) ^ (rl0 & 7)) << 4) + tg * 4;
                STSU32(a, pack_h2(S[n][0], S[n][1]));
                STSU32(a + 1024, pack_h2(S[n][2], S[n][3]));
            }
            __syncwarp();   // P visible to own-warp LDSM in PV phase
        } else {
            // ---- PV over both j-halves: A = P half, B = V half (trans) ----
#pragma unroll
            for (int kt = 0; kt < 2; kt++) {
                const uint32_t sAp = sb + FSM_P + kt * 16384;
                const uint32_t sBb = slot + kt * 16384;
#pragma unroll
                for (int ks = 0; ks < 4; ks++) {
                    uint32_t af[4];
                    LDSM_X4(af, sAp + rowAf + unitA[ks]);
                    uint32_t bfr[8][4];
#pragma unroll
                    for (int p = 0; p < 8; p++)
                        LDSM_X4_T(bfr[p], sBb + ks * 4096 + vtoff[p]);
#pragma unroll
                    for (int n = 0; n < 16; n++)
                        MMA_F16(O[n], af, &bfr[n >> 1][(n & 1) * 2]);
                }
            }
        }
    }
#undef ISSUE_CHUNK

    // epilogue: normalize, store fp16 to g_attn
    const float inv0 = 1.0f / lsum0;
    const float inv1 = 1.0f / lsum1;
    const int gr0 = itile * 128 + rl0;
    const int gr1 = itile * 128 + rl1;
#pragma unroll
    for (int n = 0; n < 16; n++) {
        const int col = h * HD + n * 8 + 2 * tg;
        *(uint32_t*)(g_attn + (size_t)gr0 * DIMC + col) =
            pack_h2(O[n][0] * inv0, O[n][1] * inv0);
        *(uint32_t*)(g_attn + (size_t)gr1 * DIMC + col) =
            pack_h2(O[n][2] * inv1, O[n][3] * inv1);
    }
}

// ---------------------------------------------------------------------------
// Fused fp32 -> fp16 convert for x, W_qkv, W_o (float4 granules)
// ---------------------------------------------------------------------------
#define N4_X  (TSEQ * DIMC / 4)
#define N4_W1 (DIMC * QKVN / 4)
#define N4_W2 (DIMC * DIMC / 4)

__global__ void k_cvt_all(const float* __restrict__ sx,
                          const float* __restrict__ sw1,
                          const float* __restrict__ sw2)
{
    int i = blockIdx.x * blockDim.x + threadIdx.x;
    const float* src;
    __half* dst;
    int off;
    if (i < N4_X)              { src = sx;  dst = g_x;    off = i; }
    else if (i < N4_X + N4_W1) { src = sw1; dst = g_wqkv; off = i - N4_X; }
    else if (i < N4_X + N4_W1 + N4_W2) { src = sw2; dst = g_wo; off = i - N4_X - N4_W1; }
    else return;
    float4 v = ((const float4*)src)[off];
    uint2 o;
    o.x = pack_h2(v.x, v.y);
    o.y = pack_h2(v.z, v.w);
    ((uint2*)dst)[off] = o;
}

// ---------------------------------------------------------------------------
// Host side
// ---------------------------------------------------------------------------
extern "C" void kernel_launch(void* const* d_in, const int* in_sizes, int n_in,
                              void* d_out, int out_size)
{
    const float* x    = (const float*)d_in[0];
    const float* Wqkv = (const float*)d_in[1];
    const float* Wo   = (const float*)d_in[2];

    void *px, *pwqkv, *pwo, *pqkv, *pattn;
    cudaGetSymbolAddress(&px, g_x);
    cudaGetSymbolAddress(&pwqkv, g_wqkv);
    cudaGetSymbolAddress(&pwo, g_wo);
    cudaGetSymbolAddress(&pqkv, g_qkv);
    cudaGetSymbolAddress(&pattn, g_attn);

    const int smemSz = STAGES * STAGEB;   // 128 KB
    cudaFuncSetAttribute(gemm_h, cudaFuncAttributeMaxDynamicSharedMemorySize, smemSz);
    cudaFuncSetAttribute(flash_attn, cudaFuncAttributeMaxDynamicSharedMemorySize, FSM_TOTAL);

    // 1) fused fp32 -> fp16 conversion (x, W_qkv, W_o)
    {
        const int total = N4_X + N4_W1 + N4_W2;
        k_cvt_all<<<(total + 255) / 256, 256>>>(x, Wqkv, Wo);
    }

    // 2) qkv = x_h @ W_qkv  [2048,3072] (fp16 out)
    gemm_h<<<dim3(QKVN / 128, TSEQ / 128), 256, smemSz>>>(
        (const __half*)px, DIMC, (const __half*)pwqkv, QKVN,
        pqkv, QKVN, DIMC, 1);

    // 3) fused causal attention -> g_attn (fp16)
    flash_attn<<<dim3(TSEQ / 128, NH), 256, FSM_TOTAL>>>();

    // 4) out = attn @ W_o (fp32 out)
    gemm_h<<<dim3(DIMC / 128, TSEQ / 128), 256, smemSz>>>(
        (const __half*)pattn, DIMC, (const __half*)pwo, DIMC,
        d_out, DIMC, DIMC, 0);
}